// round 1
// baseline (speedup 1.0000x reference)
#include <cuda_runtime.h>
#include <cuda_bf16.h>
#include <math.h>

// Problem constants
#define NSITES 1024
#define NCODES 16            // 4-site blocks: 2^4 codes
#define REGS_PER_LANE 16     // B-fragment regs per thread per code

// Precomputed block-deviation table, stored in B-fragment register order:
// u32 index = code*512 + q*128 + lane*4 + j   (q = reg/4, j = reg%4)
// reg index r = kc*8 + nt*2 + h ; value = bf16x2{ lo = Y[16kc+2tig+8h][8nt+g],
//                                                 hi = Y[16kc+2tig+8h+1][8nt+g] }
__device__ unsigned int g_table[NCODES * 512];

// ---------------------------------------------------------------------------
// Precompute kernel: one block per code c. Computes P = A[b0]@A[b1]@A[b2]@A[b3]
// in fp32, then stores Y = P - I as bf16 B-fragments in g_table.
// ---------------------------------------------------------------------------
__global__ void build_table_kernel(const float* __restrict__ A) {
    __shared__ float M[2][32][32];
    __shared__ float P[2][32][32];
    const int tid = threadIdx.x;          // 1024 threads
    const int r = tid >> 5, c = tid & 31;

    M[0][r][c] = A[r * 32 + c];
    M[1][r][c] = A[1024 + r * 32 + c];
    __syncthreads();

    const int code = blockIdx.x;
    P[0][r][c] = M[code & 1][r][c];
    __syncthreads();

    int cur = 0;
    for (int t = 1; t < 4; t++) {
        const int bsel = (code >> t) & 1;
        float acc = 0.f;
        #pragma unroll
        for (int k = 0; k < 32; k++) acc += P[cur][r][k] * M[bsel][k][c];
        P[1 - cur][r][c] = acc;
        cur ^= 1;
        __syncthreads();
    }
    // cur == 1 after 3 toggles; P[cur] holds the 4-site product.
    if (tid < 512) {
        const int l = tid >> 4;           // lane 0..31
        const int ridx = tid & 15;        // reg 0..15
        const int tig = l & 3, g = l >> 2;
        const int kc = ridx >> 3, nt = (ridx >> 1) & 3, h = ridx & 1;
        const int row = 16 * kc + 2 * tig + 8 * h;
        const int col = 8 * nt + g;
        const float lo = P[cur][row][col]     - (row     == col ? 1.f : 0.f);
        const float hi = P[cur][row + 1][col] - (row + 1 == col ? 1.f : 0.f);
        unsigned v;
        asm("cvt.rn.bf16x2.f32 %0, %1, %2;" : "=r"(v) : "f"(hi), "f"(lo));
        const int q = ridx >> 2, j = ridx & 3;
        g_table[code * 512 + q * 128 + l * 4 + j] = v;
    }
}

// ---------------------------------------------------------------------------
// Main kernel: one warp per sample. X = M - I kept as 8 m16n8 fp32 accumulator
// fragments (32 floats/thread). Per 4-site block:
//   X <- mma( bf16(X)+I , bf16(Y_code) ) + X   ==  X + Y + X@Y  (exact M(I+Y))
// ---------------------------------------------------------------------------
#define MMA_BF16(D0, D1, D2, D3, A0, A1, A2, A3, B0, B1)                      \
    asm volatile(                                                             \
        "mma.sync.aligned.m16n8k16.row.col.f32.bf16.bf16.f32 "                \
        "{%0,%1,%2,%3}, {%4,%5,%6,%7}, {%8,%9}, {%0,%1,%2,%3};"               \
        : "+f"(D0), "+f"(D1), "+f"(D2), "+f"(D3)                              \
        : "r"(A0), "r"(A1), "r"(A2), "r"(A3), "r"(B0), "r"(B1))

__global__ void __launch_bounds__(128) mps_kernel(const float* __restrict__ s,
                                                  float* __restrict__ out) {
    __shared__ uint4 tab[NCODES * 128];   // 32 KB, B-frag order [code][q][lane]

    {   // cooperative copy of the table into shared memory
        const uint4* gt = reinterpret_cast<const uint4*>(g_table);
        for (int i = threadIdx.x; i < NCODES * 128; i += 128) tab[i] = gt[i];
    }
    __syncthreads();

    const int lane = threadIdx.x & 31;
    const int warp = threadIdx.x >> 5;
    const int b = blockIdx.x * 4 + warp;  // sample index, < 4096
    const int g = lane >> 2, tig = lane & 3;

    // Per-thread packed-bf16 identity contribution for each A-fragment reg.
    unsigned idadd[16];
    #pragma unroll
    for (int mt = 0; mt < 2; mt++)
        #pragma unroll
        for (int kc = 0; kc < 2; kc++)
            #pragma unroll
            for (int j = 0; j < 4; j++) {
                const int o = j >> 1, ih = j & 1;
                const int row = g + 8 * ih + 16 * mt;
                const int col = 8 * (2 * kc + o) + 2 * tig;
                unsigned v = 0;
                if (row == col)     v |= 0x00003F80u;  // bf16 1.0 in lo half
                if (row == col + 1) v |= 0x3F800000u;  // bf16 1.0 in hi half
                idadd[mt * 8 + kc * 4 + j] = v;
            }

    // X fragments, index (mt, nt, i) -> mt*16 + nt*4 + i
    float x[32];
    #pragma unroll
    for (int i = 0; i < 32; i++) x[i] = 0.f;

    const float* srow = s + (size_t)b * NSITES;

    for (int jblk = 0; jblk < 32; jblk++) {
        const float sv = srow[jblk * 32 + lane];
        const unsigned m = __ballot_sync(0xffffffffu, sv > 0.f);

        #pragma unroll
        for (int k = 0; k < 8; k++) {
            const int code = (m >> (4 * k)) & 0xF;

            // Load B fragments (16 u32) — conflict-free LDS.128 x4
            unsigned bb[16];
            {
                const uint4* p = tab + (code << 7) + lane;
                const uint4 t0 = p[0];
                const uint4 t1 = p[32];
                const uint4 t2 = p[64];
                const uint4 t3 = p[96];
                bb[0]  = t0.x; bb[1]  = t0.y; bb[2]  = t0.z; bb[3]  = t0.w;
                bb[4]  = t1.x; bb[5]  = t1.y; bb[6]  = t1.z; bb[7]  = t1.w;
                bb[8]  = t2.x; bb[9]  = t2.y; bb[10] = t2.z; bb[11] = t2.w;
                bb[12] = t3.x; bb[13] = t3.y; bb[14] = t3.z; bb[15] = t3.w;
            }

            // Build A fragments = bf16(X) + I
            unsigned a[16];
            #pragma unroll
            for (int mt = 0; mt < 2; mt++)
                #pragma unroll
                for (int kc = 0; kc < 2; kc++)
                    #pragma unroll
                    for (int j = 0; j < 4; j++) {
                        const int o = j >> 1, ih = j & 1;
                        const int xi = mt * 16 + (2 * kc + o) * 4 + 2 * ih;
                        unsigned av;
                        asm("cvt.rn.bf16x2.f32 %0, %1, %2;"
                            : "=r"(av) : "f"(x[xi + 1]), "f"(x[xi]));
                        asm("add.bf16x2 %0, %0, %1;"
                            : "+r"(av) : "r"(idadd[mt * 8 + kc * 4 + j]));
                        a[mt * 8 + kc * 4 + j] = av;
                    }

            // X = (I + X~) @ Y~ + X : 8 output tiles x 2 k-chunks
            #pragma unroll
            for (int mt = 0; mt < 2; mt++)
                #pragma unroll
                for (int nt = 0; nt < 4; nt++) {
                    MMA_BF16(x[mt*16 + nt*4 + 0], x[mt*16 + nt*4 + 1],
                             x[mt*16 + nt*4 + 2], x[mt*16 + nt*4 + 3],
                             a[mt*8 + 0], a[mt*8 + 1], a[mt*8 + 2], a[mt*8 + 3],
                             bb[nt*2], bb[nt*2 + 1]);
                    MMA_BF16(x[mt*16 + nt*4 + 0], x[mt*16 + nt*4 + 1],
                             x[mt*16 + nt*4 + 2], x[mt*16 + nt*4 + 3],
                             a[mt*8 + 4], a[mt*8 + 5], a[mt*8 + 6], a[mt*8 + 7],
                             bb[8 + nt*2], bb[8 + nt*2 + 1]);
                }
        }
    }

    // trace(M) = 32 + trace(X); pick this thread's diagonal elements
    float tr = 0.f;
    #pragma unroll
    for (int mt = 0; mt < 2; mt++)
        #pragma unroll
        for (int nt = 0; nt < 4; nt++)
            #pragma unroll
            for (int i = 0; i < 4; i++) {
                const int row = g + 8 * (i >> 1) + 16 * mt;
                const int col = 8 * nt + 2 * tig + (i & 1);
                if (row == col) tr += x[mt * 16 + nt * 4 + i];
            }
    #pragma unroll
    for (int off = 16; off; off >>= 1)
        tr += __shfl_xor_sync(0xffffffffu, tr, off);

    if (lane == 0) out[b] = logf(32.f + tr);
}

// ---------------------------------------------------------------------------
extern "C" void kernel_launch(void* const* d_in, const int* in_sizes, int n_in,
                              void* d_out, int out_size) {
    const float* s = (const float*)d_in[0];   // [4096, 1024] fp32
    const float* A = (const float*)d_in[1];   // [2, 32, 32] fp32
    float* out = (float*)d_out;               // [4096] fp32

    build_table_kernel<<<16, 1024>>>(A);
    mps_kernel<<<1024, 128>>>(s, out);
}

// round 2
// speedup vs baseline: 1.2328x; 1.2328x over previous
#include <cuda_runtime.h>
#include <cuda_bf16.h>
#include <math.h>

// Problem constants
#define NSITES 1024
#define NC6 64               // 6-site blocks: 2^6 codes
#define NC4 16               // 4-site tail block: 2^4 codes
// table entry layout (per code): 512 u32 = 128 uint4, B-fragment order
//   u32 index = q*128 + lane*4 + j   (reg r = q*4+j = kc*8 + nt*2 + h)
//   value = bf16x2{ lo = Y[16kc+2tig+8h][8nt+g], hi = Y[...+1][8nt+g] }
__device__ unsigned int g_table[(NC6 + NC4) * 512];   // 6-table then 4-table

// ---------------------------------------------------------------------------
// Precompute: block 0..63 -> 6-site products, block 64..79 -> 4-site products.
// P = A[b0]@A[b1]@...@A[b_{n-1}] in fp32, store Y = P - I as bf16 B-fragments.
// ---------------------------------------------------------------------------
__global__ void build_table_kernel(const float* __restrict__ A) {
    __shared__ float M[2][32][32];
    __shared__ float P[2][32][32];
    const int tid = threadIdx.x;          // 1024 threads
    const int r = tid >> 5, c = tid & 31;

    M[0][r][c] = A[r * 32 + c];
    M[1][r][c] = A[1024 + r * 32 + c];
    __syncthreads();

    const bool is6 = blockIdx.x < NC6;
    const int code = is6 ? blockIdx.x : (blockIdx.x - NC6);
    const int nsit = is6 ? 6 : 4;

    P[0][r][c] = M[code & 1][r][c];
    __syncthreads();

    int cur = 0;
    for (int t = 1; t < nsit; t++) {
        const int bsel = (code >> t) & 1;
        float acc = 0.f;
        #pragma unroll
        for (int k = 0; k < 32; k++) acc += P[cur][r][k] * M[bsel][k][c];
        P[1 - cur][r][c] = acc;
        cur ^= 1;
        __syncthreads();
    }
    // after nsit-1 toggles, P[cur] holds the product (cur = (nsit-1)&1)
    if (tid < 512) {
        const int l = tid >> 4;           // lane 0..31
        const int ridx = tid & 15;        // reg 0..15
        const int tig = l & 3, g = l >> 2;
        const int kc = ridx >> 3, nt = (ridx >> 1) & 3, h = ridx & 1;
        const int row = 16 * kc + 2 * tig + 8 * h;
        const int col = 8 * nt + g;
        const float lo = P[cur][row][col]     - (row     == col ? 1.f : 0.f);
        const float hi = P[cur][row + 1][col] - (row + 1 == col ? 1.f : 0.f);
        unsigned v;
        asm("cvt.rn.bf16x2.f32 %0, %1, %2;" : "=r"(v) : "f"(hi), "f"(lo));
        const int q = ridx >> 2, j = ridx & 3;
        g_table[blockIdx.x * 512 + q * 128 + l * 4 + j] = v;
    }
}

// ---------------------------------------------------------------------------
// Main kernel: one warp per sample. X = M - I as 8 m16n8 fp32 acc fragments.
// Per block step:  X <- mma( bf16(X)+I , bf16(Y_code) ) + X  ==  X + Y + X@Y
// ---------------------------------------------------------------------------
#define MMA_BF16(D0, D1, D2, D3, A0, A1, A2, A3, B0, B1)                      \
    asm volatile(                                                             \
        "mma.sync.aligned.m16n8k16.row.col.f32.bf16.bf16.f32 "                \
        "{%0,%1,%2,%3}, {%4,%5,%6,%7}, {%8,%9}, {%0,%1,%2,%3};"               \
        : "+f"(D0), "+f"(D1), "+f"(D2), "+f"(D3)                              \
        : "r"(A0), "r"(A1), "r"(A2), "r"(A3), "r"(B0), "r"(B1))

__device__ __forceinline__ void do_step(const uint4* __restrict__ p,
                                        float x[32],
                                        const unsigned idadd[16]) {
    // Load B fragments (16 u32) — conflict-free LDS.128 x4
    unsigned bb[16];
    {
        const uint4 t0 = p[0];
        const uint4 t1 = p[32];
        const uint4 t2 = p[64];
        const uint4 t3 = p[96];
        bb[0]  = t0.x; bb[1]  = t0.y; bb[2]  = t0.z; bb[3]  = t0.w;
        bb[4]  = t1.x; bb[5]  = t1.y; bb[6]  = t1.z; bb[7]  = t1.w;
        bb[8]  = t2.x; bb[9]  = t2.y; bb[10] = t2.z; bb[11] = t2.w;
        bb[12] = t3.x; bb[13] = t3.y; bb[14] = t3.z; bb[15] = t3.w;
    }

    // Build A fragments = bf16(X) + I
    unsigned a[16];
    #pragma unroll
    for (int mt = 0; mt < 2; mt++)
        #pragma unroll
        for (int kc = 0; kc < 2; kc++)
            #pragma unroll
            for (int j = 0; j < 4; j++) {
                const int o = j >> 1, ih = j & 1;
                const int xi = mt * 16 + (2 * kc + o) * 4 + 2 * ih;
                unsigned av;
                asm("cvt.rn.bf16x2.f32 %0, %1, %2;"
                    : "=r"(av) : "f"(x[xi + 1]), "f"(x[xi]));
                asm("add.bf16x2 %0, %0, %1;"
                    : "+r"(av) : "r"(idadd[mt * 8 + kc * 4 + j]));
                a[mt * 8 + kc * 4 + j] = av;
            }

    // X = (I + X~) @ Y~ + X : 8 output tiles x 2 k-chunks
    #pragma unroll
    for (int mt = 0; mt < 2; mt++)
        #pragma unroll
        for (int nt = 0; nt < 4; nt++) {
            MMA_BF16(x[mt*16 + nt*4 + 0], x[mt*16 + nt*4 + 1],
                     x[mt*16 + nt*4 + 2], x[mt*16 + nt*4 + 3],
                     a[mt*8 + 0], a[mt*8 + 1], a[mt*8 + 2], a[mt*8 + 3],
                     bb[nt*2], bb[nt*2 + 1]);
            MMA_BF16(x[mt*16 + nt*4 + 0], x[mt*16 + nt*4 + 1],
                     x[mt*16 + nt*4 + 2], x[mt*16 + nt*4 + 3],
                     a[mt*8 + 4], a[mt*8 + 5], a[mt*8 + 6], a[mt*8 + 7],
                     bb[8 + nt*2], bb[8 + nt*2 + 1]);
        }
}

#define SMEM_BYTES ((NC6 + NC4) * 512 * 4)   // 160 KB

__global__ void __launch_bounds__(512, 1)
mps_kernel(const float* __restrict__ s, float* __restrict__ out) {
    extern __shared__ uint4 tab[];        // [(64+16)*128] uint4, 160 KB

    {   // cooperative copy of both tables into shared memory
        const uint4* gt = reinterpret_cast<const uint4*>(g_table);
        for (int i = threadIdx.x; i < (NC6 + NC4) * 128; i += 512) tab[i] = gt[i];
    }
    __syncthreads();

    const int lane = threadIdx.x & 31;
    const int warp = threadIdx.x >> 5;
    const int b = blockIdx.x * 16 + warp;   // sample index, < 4096
    const int g = lane >> 2, tig = lane & 3;

    // Per-thread packed-bf16 identity contribution for each A-fragment reg.
    unsigned idadd[16];
    #pragma unroll
    for (int mt = 0; mt < 2; mt++)
        #pragma unroll
        for (int kc = 0; kc < 2; kc++)
            #pragma unroll
            for (int j = 0; j < 4; j++) {
                const int o = j >> 1, ih = j & 1;
                const int row = g + 8 * ih + 16 * mt;
                const int col = 8 * (2 * kc + o) + 2 * tig;
                unsigned v = 0;
                if (row == col)     v |= 0x00003F80u;  // bf16 1.0 in lo half
                if (row == col + 1) v |= 0x3F800000u;  // bf16 1.0 in hi half
                idadd[mt * 8 + kc * 4 + j] = v;
            }

    // X fragments, index (mt, nt, i) -> mt*16 + nt*4 + i
    float x[32];
    #pragma unroll
    for (int i = 0; i < 32; i++) x[i] = 0.f;

    const float* srow = s + (size_t)b * NSITES;

    // 10 chunks of 96 sites = 16 six-site codes each (960 sites)
    for (int chunk = 0; chunk < 10; chunk++) {
        const int base = chunk * 96;
        const unsigned m0 = __ballot_sync(0xffffffffu, srow[base      + lane] > 0.f);
        const unsigned m1 = __ballot_sync(0xffffffffu, srow[base + 32 + lane] > 0.f);
        const unsigned m2 = __ballot_sync(0xffffffffu, srow[base + 64 + lane] > 0.f);
        const unsigned long long u01 = (unsigned long long)m0 |
                                       ((unsigned long long)m1 << 32);
        const unsigned long long u12 = (unsigned long long)m1 |
                                       ((unsigned long long)m2 << 32);
        #pragma unroll
        for (int k = 0; k < 16; k++) {
            int code;
            if (k < 10) code = (int)((u01 >> (6 * k)) & 63ull);
            else        code = (int)((u12 >> (6 * k - 32)) & 63ull);
            do_step(tab + code * 128 + lane, x, idadd);
        }
    }

    // tail: 64 sites = 10 six-site codes + 1 four-site code
    {
        const int base = 960;
        const unsigned m0 = __ballot_sync(0xffffffffu, srow[base      + lane] > 0.f);
        const unsigned m1 = __ballot_sync(0xffffffffu, srow[base + 32 + lane] > 0.f);
        const unsigned long long u01 = (unsigned long long)m0 |
                                       ((unsigned long long)m1 << 32);
        #pragma unroll
        for (int k = 0; k < 10; k++) {
            const int code = (int)((u01 >> (6 * k)) & 63ull);
            do_step(tab + code * 128 + lane, x, idadd);
        }
        const int c4 = (int)((u01 >> 60) & 15ull);
        do_step(tab + NC6 * 128 + c4 * 128 + lane, x, idadd);
    }

    // trace(M) = 32 + trace(X); pick this thread's diagonal elements
    float tr = 0.f;
    #pragma unroll
    for (int mt = 0; mt < 2; mt++)
        #pragma unroll
        for (int nt = 0; nt < 4; nt++)
            #pragma unroll
            for (int i = 0; i < 4; i++) {
                const int row = g + 8 * (i >> 1) + 16 * mt;
                const int col = 8 * nt + 2 * tig + (i & 1);
                if (row == col) tr += x[mt * 16 + nt * 4 + i];
            }
    #pragma unroll
    for (int off = 16; off; off >>= 1)
        tr += __shfl_xor_sync(0xffffffffu, tr, off);

    if (lane == 0) out[b] = logf(32.f + tr);
}

// ---------------------------------------------------------------------------
extern "C" void kernel_launch(void* const* d_in, const int* in_sizes, int n_in,
                              void* d_out, int out_size) {
    const float* s = (const float*)d_in[0];   // [4096, 1024] fp32
    const float* A = (const float*)d_in[1];   // [2, 32, 32] fp32
    float* out = (float*)d_out;               // [4096] fp32

    static bool attr_set = false;
    if (!attr_set) {
        cudaFuncSetAttribute(mps_kernel,
                             cudaFuncAttributeMaxDynamicSharedMemorySize,
                             SMEM_BYTES);
        attr_set = true;
    }

    build_table_kernel<<<NC6 + NC4, 1024>>>(A);
    mps_kernel<<<256, 512, SMEM_BYTES>>>(s, out);
}

// round 3
// speedup vs baseline: 1.2884x; 1.0451x over previous
#include <cuda_runtime.h>
#include <cuda_bf16.h>
#include <math.h>

// Problem constants
#define NSITES 1024
#define NC6 64               // 6-site blocks: 2^6 codes
#define NC4 16               // 4-site tail block: 2^4 codes
// table entry layout (per code): 512 u32 = 128 uint4, B-fragment order
__device__ unsigned int g_table[(NC6 + NC4) * 512];   // 6-table then 4-table

// ---------------------------------------------------------------------------
// Precompute: block 0..63 -> 6-site products, block 64..79 -> 4-site products.
// ---------------------------------------------------------------------------
__global__ void build_table_kernel(const float* __restrict__ A) {
    __shared__ float M[2][32][32];
    __shared__ float P[2][32][32];
    const int tid = threadIdx.x;          // 1024 threads
    const int r = tid >> 5, c = tid & 31;

    M[0][r][c] = A[r * 32 + c];
    M[1][r][c] = A[1024 + r * 32 + c];
    __syncthreads();

    const bool is6 = blockIdx.x < NC6;
    const int code = is6 ? blockIdx.x : (blockIdx.x - NC6);
    const int nsit = is6 ? 6 : 4;

    P[0][r][c] = M[code & 1][r][c];
    __syncthreads();

    int cur = 0;
    for (int t = 1; t < nsit; t++) {
        const int bsel = (code >> t) & 1;
        float acc = 0.f;
        #pragma unroll
        for (int k = 0; k < 32; k++) acc += P[cur][r][k] * M[bsel][k][c];
        P[1 - cur][r][c] = acc;
        cur ^= 1;
        __syncthreads();
    }
    if (tid < 512) {
        const int l = tid >> 4;           // lane
        const int ridx = tid & 15;        // reg 0..15
        const int tig = l & 3, g = l >> 2;
        const int kc = ridx >> 3, nt = (ridx >> 1) & 3, h = ridx & 1;
        const int row = 16 * kc + 2 * tig + 8 * h;
        const int col = 8 * nt + g;
        const float lo = P[cur][row][col]     - (row     == col ? 1.f : 0.f);
        const float hi = P[cur][row + 1][col] - (row + 1 == col ? 1.f : 0.f);
        unsigned v;
        asm("cvt.rn.bf16x2.f32 %0, %1, %2;" : "=r"(v) : "f"(hi), "f"(lo));
        const int q = ridx >> 2, j = ridx & 3;
        g_table[blockIdx.x * 512 + q * 128 + l * 4 + j] = v;
    }
}

// ---------------------------------------------------------------------------
// Main kernel: one warp per TWO samples, interleaved for ILP.
// X = M - I as 8 m16n8 fp32 acc fragments per sample.
// Per step:  X <- mma( bf16(X)+I , bf16(Y_code) ) + X  ==  X + Y + X@Y
// ---------------------------------------------------------------------------
#define MMA_BF16(D0, D1, D2, D3, A0, A1, A2, A3, B0, B1)                      \
    asm volatile(                                                             \
        "mma.sync.aligned.m16n8k16.row.col.f32.bf16.bf16.f32 "                \
        "{%0,%1,%2,%3}, {%4,%5,%6,%7}, {%8,%9}, {%0,%1,%2,%3};"               \
        : "+f"(D0), "+f"(D1), "+f"(D2), "+f"(D3)                              \
        : "r"(A0), "r"(A1), "r"(A2), "r"(A3), "r"(B0), "r"(B1))

__device__ __forceinline__ void do_step(const uint4* __restrict__ p,
                                        float x[32],
                                        const unsigned idadd[16]) {
    // Build ALL A fragments first (must read pre-step X)
    unsigned a[16];
    #pragma unroll
    for (int mt = 0; mt < 2; mt++)
        #pragma unroll
        for (int kc = 0; kc < 2; kc++)
            #pragma unroll
            for (int j = 0; j < 4; j++) {
                const int o = j >> 1, ih = j & 1;
                const int xi = mt * 16 + (2 * kc + o) * 4 + 2 * ih;
                unsigned av;
                asm("cvt.rn.bf16x2.f32 %0, %1, %2;"
                    : "=r"(av) : "f"(x[xi + 1]), "f"(x[xi]));
                asm("add.bf16x2 %0, %0, %1;"
                    : "+r"(av) : "r"(idadd[mt * 8 + kc * 4 + j]));
                a[mt * 8 + kc * 4 + j] = av;
            }

    // kc=0 half: load 8 B regs, 8 MMAs
    {
        const uint4 t0 = p[0];
        const uint4 t1 = p[32];
        #pragma unroll
        for (int mt = 0; mt < 2; mt++) {
            MMA_BF16(x[mt*16 + 0], x[mt*16 + 1], x[mt*16 + 2], x[mt*16 + 3],
                     a[mt*8+0], a[mt*8+1], a[mt*8+2], a[mt*8+3], t0.x, t0.y);
            MMA_BF16(x[mt*16 + 4], x[mt*16 + 5], x[mt*16 + 6], x[mt*16 + 7],
                     a[mt*8+0], a[mt*8+1], a[mt*8+2], a[mt*8+3], t0.z, t0.w);
            MMA_BF16(x[mt*16 + 8], x[mt*16 + 9], x[mt*16 +10], x[mt*16 +11],
                     a[mt*8+0], a[mt*8+1], a[mt*8+2], a[mt*8+3], t1.x, t1.y);
            MMA_BF16(x[mt*16 +12], x[mt*16 +13], x[mt*16 +14], x[mt*16 +15],
                     a[mt*8+0], a[mt*8+1], a[mt*8+2], a[mt*8+3], t1.z, t1.w);
        }
    }
    // kc=1 half
    {
        const uint4 t2 = p[64];
        const uint4 t3 = p[96];
        #pragma unroll
        for (int mt = 0; mt < 2; mt++) {
            MMA_BF16(x[mt*16 + 0], x[mt*16 + 1], x[mt*16 + 2], x[mt*16 + 3],
                     a[mt*8+4], a[mt*8+5], a[mt*8+6], a[mt*8+7], t2.x, t2.y);
            MMA_BF16(x[mt*16 + 4], x[mt*16 + 5], x[mt*16 + 6], x[mt*16 + 7],
                     a[mt*8+4], a[mt*8+5], a[mt*8+6], a[mt*8+7], t2.z, t2.w);
            MMA_BF16(x[mt*16 + 8], x[mt*16 + 9], x[mt*16 +10], x[mt*16 +11],
                     a[mt*8+4], a[mt*8+5], a[mt*8+6], a[mt*8+7], t3.x, t3.y);
            MMA_BF16(x[mt*16 +12], x[mt*16 +13], x[mt*16 +14], x[mt*16 +15],
                     a[mt*8+4], a[mt*8+5], a[mt*8+6], a[mt*8+7], t3.z, t3.w);
        }
    }
}

#define SMEM_BYTES ((NC6 + NC4) * 512 * 4)   // 160 KB

__global__ void __launch_bounds__(512, 1)
mps_kernel(const float* __restrict__ s, float* __restrict__ out) {
    extern __shared__ uint4 tab[];        // [(64+16)*128] uint4, 160 KB

    {   // cooperative copy of both tables into shared memory
        const uint4* gt = reinterpret_cast<const uint4*>(g_table);
        for (int i = threadIdx.x; i < (NC6 + NC4) * 128; i += 512) tab[i] = gt[i];
    }
    __syncthreads();

    const int lane = threadIdx.x & 31;
    const int warp = threadIdx.x >> 5;
    const int b0 = blockIdx.x * 32 + warp * 2;   // two samples per warp
    const int g = lane >> 2, tig = lane & 3;

    // Per-thread packed-bf16 identity contribution for each A-fragment reg.
    unsigned idadd[16];
    #pragma unroll
    for (int mt = 0; mt < 2; mt++)
        #pragma unroll
        for (int kc = 0; kc < 2; kc++)
            #pragma unroll
            for (int j = 0; j < 4; j++) {
                const int o = j >> 1, ih = j & 1;
                const int row = g + 8 * ih + 16 * mt;
                const int col = 8 * (2 * kc + o) + 2 * tig;
                unsigned v = 0;
                if (row == col)     v |= 0x00003F80u;  // bf16 1.0 lo half
                if (row == col + 1) v |= 0x3F800000u;  // bf16 1.0 hi half
                idadd[mt * 8 + kc * 4 + j] = v;
            }

    float x0[32], x1[32];
    #pragma unroll
    for (int i = 0; i < 32; i++) { x0[i] = 0.f; x1[i] = 0.f; }

    const float* srow0 = s + (size_t)b0 * NSITES;
    const float* srow1 = srow0 + NSITES;

    // 10 chunks of 96 sites = 16 six-site codes each (960 sites)
    for (int chunk = 0; chunk < 10; chunk++) {
        const int base = chunk * 96;
        const unsigned p0 = __ballot_sync(0xffffffffu, srow0[base      + lane] > 0.f);
        const unsigned p1 = __ballot_sync(0xffffffffu, srow0[base + 32 + lane] > 0.f);
        const unsigned p2 = __ballot_sync(0xffffffffu, srow0[base + 64 + lane] > 0.f);
        const unsigned q0 = __ballot_sync(0xffffffffu, srow1[base      + lane] > 0.f);
        const unsigned q1 = __ballot_sync(0xffffffffu, srow1[base + 32 + lane] > 0.f);
        const unsigned q2 = __ballot_sync(0xffffffffu, srow1[base + 64 + lane] > 0.f);
        const unsigned long long s0a = (unsigned long long)p0 | ((unsigned long long)p1 << 32);
        const unsigned long long s0b = (unsigned long long)p1 | ((unsigned long long)p2 << 32);
        const unsigned long long s1a = (unsigned long long)q0 | ((unsigned long long)q1 << 32);
        const unsigned long long s1b = (unsigned long long)q1 | ((unsigned long long)q2 << 32);
        #pragma unroll
        for (int k = 0; k < 16; k++) {
            int c0, c1;
            if (k < 10) { c0 = (int)((s0a >> (6 * k)) & 63ull);
                          c1 = (int)((s1a >> (6 * k)) & 63ull); }
            else        { c0 = (int)((s0b >> (6 * k - 32)) & 63ull);
                          c1 = (int)((s1b >> (6 * k - 32)) & 63ull); }
            do_step(tab + c0 * 128 + lane, x0, idadd);
            do_step(tab + c1 * 128 + lane, x1, idadd);
        }
    }

    // tail: 64 sites = 10 six-site codes + 1 four-site code
    {
        const int base = 960;
        const unsigned p0 = __ballot_sync(0xffffffffu, srow0[base      + lane] > 0.f);
        const unsigned p1 = __ballot_sync(0xffffffffu, srow0[base + 32 + lane] > 0.f);
        const unsigned q0 = __ballot_sync(0xffffffffu, srow1[base      + lane] > 0.f);
        const unsigned q1 = __ballot_sync(0xffffffffu, srow1[base + 32 + lane] > 0.f);
        const unsigned long long s0a = (unsigned long long)p0 | ((unsigned long long)p1 << 32);
        const unsigned long long s1a = (unsigned long long)q0 | ((unsigned long long)q1 << 32);
        #pragma unroll
        for (int k = 0; k < 10; k++) {
            const int c0 = (int)((s0a >> (6 * k)) & 63ull);
            const int c1 = (int)((s1a >> (6 * k)) & 63ull);
            do_step(tab + c0 * 128 + lane, x0, idadd);
            do_step(tab + c1 * 128 + lane, x1, idadd);
        }
        const int c40 = (int)((s0a >> 60) & 15ull);
        const int c41 = (int)((s1a >> 60) & 15ull);
        do_step(tab + (NC6 + c40) * 128 + lane, x0, idadd);
        do_step(tab + (NC6 + c41) * 128 + lane, x1, idadd);
    }

    // trace(M) = 32 + trace(X); pick this thread's diagonal elements
    float tr0 = 0.f, tr1 = 0.f;
    #pragma unroll
    for (int mt = 0; mt < 2; mt++)
        #pragma unroll
        for (int nt = 0; nt < 4; nt++)
            #pragma unroll
            for (int i = 0; i < 4; i++) {
                const int row = g + 8 * (i >> 1) + 16 * mt;
                const int col = 8 * nt + 2 * tig + (i & 1);
                if (row == col) { tr0 += x0[mt*16 + nt*4 + i];
                                  tr1 += x1[mt*16 + nt*4 + i]; }
            }
    #pragma unroll
    for (int off = 16; off; off >>= 1) {
        tr0 += __shfl_xor_sync(0xffffffffu, tr0, off);
        tr1 += __shfl_xor_sync(0xffffffffu, tr1, off);
    }

    if (lane == 0) {
        out[b0]     = logf(32.f + tr0);
        out[b0 + 1] = logf(32.f + tr1);
    }
}

// ---------------------------------------------------------------------------
extern "C" void kernel_launch(void* const* d_in, const int* in_sizes, int n_in,
                              void* d_out, int out_size) {
    const float* s = (const float*)d_in[0];   // [4096, 1024] fp32
    const float* A = (const float*)d_in[1];   // [2, 32, 32] fp32
    float* out = (float*)d_out;               // [4096] fp32

    static bool attr_set = false;
    if (!attr_set) {
        cudaFuncSetAttribute(mps_kernel,
                             cudaFuncAttributeMaxDynamicSharedMemorySize,
                             SMEM_BYTES);
        attr_set = true;
    }

    build_table_kernel<<<NC6 + NC4, 1024>>>(A);
    mps_kernel<<<128, 512, SMEM_BYTES>>>(s, out);
}

// round 4
// speedup vs baseline: 1.4076x; 1.0925x over previous
#include <cuda_runtime.h>
#include <cuda_bf16.h>
#include <math.h>

// Problem constants
#define NSITES 1024
#define NC6 64               // 6-site blocks: 2^6 codes
#define NC4 16               // 4-site tail block: 2^4 codes
// table entry layout (per code): 512 u32 = 128 uint4, B-fragment order
__device__ unsigned int g_table[(NC6 + NC4) * 512];   // 6-table then 4-table

// ---------------------------------------------------------------------------
// Precompute: block 0..63 -> 6-site products, block 64..79 -> 4-site products.
// Stores Y = P - I as bf16 B-fragments (deviation form for the B operand).
// ---------------------------------------------------------------------------
__global__ void build_table_kernel(const float* __restrict__ A) {
    __shared__ float M[2][32][32];
    __shared__ float P[2][32][32];
    const int tid = threadIdx.x;          // 1024 threads
    const int r = tid >> 5, c = tid & 31;

    M[0][r][c] = A[r * 32 + c];
    M[1][r][c] = A[1024 + r * 32 + c];
    __syncthreads();

    const bool is6 = blockIdx.x < NC6;
    const int code = is6 ? blockIdx.x : (blockIdx.x - NC6);
    const int nsit = is6 ? 6 : 4;

    P[0][r][c] = M[code & 1][r][c];
    __syncthreads();

    int cur = 0;
    for (int t = 1; t < nsit; t++) {
        const int bsel = (code >> t) & 1;
        float acc = 0.f;
        #pragma unroll
        for (int k = 0; k < 32; k++) acc += P[cur][r][k] * M[bsel][k][c];
        P[1 - cur][r][c] = acc;
        cur ^= 1;
        __syncthreads();
    }
    if (tid < 512) {
        const int l = tid >> 4;           // lane
        const int ridx = tid & 15;        // reg 0..15
        const int tig = l & 3, g = l >> 2;
        const int kc = ridx >> 3, nt = (ridx >> 1) & 3, h = ridx & 1;
        const int row = 16 * kc + 2 * tig + 8 * h;
        const int col = 8 * nt + g;
        const float lo = P[cur][row][col]     - (row     == col ? 1.f : 0.f);
        const float hi = P[cur][row + 1][col] - (row + 1 == col ? 1.f : 0.f);
        unsigned v;
        asm("cvt.rn.bf16x2.f32 %0, %1, %2;" : "=r"(v) : "f"(hi), "f"(lo));
        const int q = ridx >> 2, j = ridx & 3;
        g_table[blockIdx.x * 512 + q * 128 + l * 4 + j] = v;
    }
}

// ---------------------------------------------------------------------------
// Main kernel: one warp per TWO samples, interleaved for ILP.
// M kept directly as 8 m16n8 fp32 acc fragments per sample (init = I).
// Per step:  M <- mma( bf16(M) , Y_code ) + M   ==  M @ (I + Y)   (C exact)
// ---------------------------------------------------------------------------
#define MMA_BF16(D0, D1, D2, D3, A0, A1, A2, A3, B0, B1)                      \
    asm volatile(                                                             \
        "mma.sync.aligned.m16n8k16.row.col.f32.bf16.bf16.f32 "                \
        "{%0,%1,%2,%3}, {%4,%5,%6,%7}, {%8,%9}, {%0,%1,%2,%3};"               \
        : "+f"(D0), "+f"(D1), "+f"(D2), "+f"(D3)                              \
        : "r"(A0), "r"(A1), "r"(A2), "r"(A3), "r"(B0), "r"(B1))

__device__ __forceinline__ void do_step(const uint4* __restrict__ p,
                                        float x[32]) {
    // Build ALL A fragments first (must read pre-step M) — bare cvt, no add
    unsigned a[16];
    #pragma unroll
    for (int mt = 0; mt < 2; mt++)
        #pragma unroll
        for (int kc = 0; kc < 2; kc++)
            #pragma unroll
            for (int j = 0; j < 4; j++) {
                const int o = j >> 1, ih = j & 1;
                const int xi = mt * 16 + (2 * kc + o) * 4 + 2 * ih;
                asm("cvt.rn.bf16x2.f32 %0, %1, %2;"
                    : "=r"(a[mt * 8 + kc * 4 + j])
                    : "f"(x[xi + 1]), "f"(x[xi]));
            }

    // kc=0 half
    {
        const uint4 t0 = p[0];
        const uint4 t1 = p[32];
        #pragma unroll
        for (int mt = 0; mt < 2; mt++) {
            MMA_BF16(x[mt*16 + 0], x[mt*16 + 1], x[mt*16 + 2], x[mt*16 + 3],
                     a[mt*8+0], a[mt*8+1], a[mt*8+2], a[mt*8+3], t0.x, t0.y);
            MMA_BF16(x[mt*16 + 4], x[mt*16 + 5], x[mt*16 + 6], x[mt*16 + 7],
                     a[mt*8+0], a[mt*8+1], a[mt*8+2], a[mt*8+3], t0.z, t0.w);
            MMA_BF16(x[mt*16 + 8], x[mt*16 + 9], x[mt*16 +10], x[mt*16 +11],
                     a[mt*8+0], a[mt*8+1], a[mt*8+2], a[mt*8+3], t1.x, t1.y);
            MMA_BF16(x[mt*16 +12], x[mt*16 +13], x[mt*16 +14], x[mt*16 +15],
                     a[mt*8+0], a[mt*8+1], a[mt*8+2], a[mt*8+3], t1.z, t1.w);
        }
    }
    // kc=1 half
    {
        const uint4 t2 = p[64];
        const uint4 t3 = p[96];
        #pragma unroll
        for (int mt = 0; mt < 2; mt++) {
            MMA_BF16(x[mt*16 + 0], x[mt*16 + 1], x[mt*16 + 2], x[mt*16 + 3],
                     a[mt*8+4], a[mt*8+5], a[mt*8+6], a[mt*8+7], t2.x, t2.y);
            MMA_BF16(x[mt*16 + 4], x[mt*16 + 5], x[mt*16 + 6], x[mt*16 + 7],
                     a[mt*8+4], a[mt*8+5], a[mt*8+6], a[mt*8+7], t2.z, t2.w);
            MMA_BF16(x[mt*16 + 8], x[mt*16 + 9], x[mt*16 +10], x[mt*16 +11],
                     a[mt*8+4], a[mt*8+5], a[mt*8+6], a[mt*8+7], t3.x, t3.y);
            MMA_BF16(x[mt*16 +12], x[mt*16 +13], x[mt*16 +14], x[mt*16 +15],
                     a[mt*8+4], a[mt*8+5], a[mt*8+6], a[mt*8+7], t3.z, t3.w);
        }
    }
}

#define SMEM_BYTES ((NC6 + NC4) * 512 * 4)   // 160 KB
#define NPAIRS 2048                           // 4096 samples / 2
#define GRID 148

__global__ void __launch_bounds__(512, 1)
mps_kernel(const float* __restrict__ s, float* __restrict__ out) {
    extern __shared__ uint4 tab[];        // [(64+16)*128] uint4, 160 KB

    {   // cooperative copy of both tables into shared memory
        const uint4* gt = reinterpret_cast<const uint4*>(g_table);
        for (int i = threadIdx.x; i < (NC6 + NC4) * 128; i += 512) tab[i] = gt[i];
    }
    __syncthreads();

    const int lane = threadIdx.x & 31;
    const int warp = threadIdx.x >> 5;
    // Balanced warp->pair map over all 148 SMs
    const int pair = warp * GRID + blockIdx.x;
    if (pair >= NPAIRS) return;
    const int b0 = pair * 2;
    const int g = lane >> 2, tig = lane & 3;

    // Init M = I in C-fragment layout
    float x0[32], x1[32];
    #pragma unroll
    for (int mt = 0; mt < 2; mt++)
        #pragma unroll
        for (int nt = 0; nt < 4; nt++)
            #pragma unroll
            for (int i = 0; i < 4; i++) {
                const int row = g + 8 * (i >> 1) + 16 * mt;
                const int col = 8 * nt + 2 * tig + (i & 1);
                const float v = (row == col) ? 1.f : 0.f;
                x0[mt*16 + nt*4 + i] = v;
                x1[mt*16 + nt*4 + i] = v;
            }

    const float* srow0 = s + (size_t)b0 * NSITES;
    const float* srow1 = srow0 + NSITES;

    // 10 chunks of 96 sites = 16 six-site codes each (960 sites)
    for (int chunk = 0; chunk < 10; chunk++) {
        const int base = chunk * 96;
        const unsigned p0 = __ballot_sync(0xffffffffu, srow0[base      + lane] > 0.f);
        const unsigned p1 = __ballot_sync(0xffffffffu, srow0[base + 32 + lane] > 0.f);
        const unsigned p2 = __ballot_sync(0xffffffffu, srow0[base + 64 + lane] > 0.f);
        const unsigned q0 = __ballot_sync(0xffffffffu, srow1[base      + lane] > 0.f);
        const unsigned q1 = __ballot_sync(0xffffffffu, srow1[base + 32 + lane] > 0.f);
        const unsigned q2 = __ballot_sync(0xffffffffu, srow1[base + 64 + lane] > 0.f);
        const unsigned long long s0a = (unsigned long long)p0 | ((unsigned long long)p1 << 32);
        const unsigned long long s0b = (unsigned long long)p1 | ((unsigned long long)p2 << 32);
        const unsigned long long s1a = (unsigned long long)q0 | ((unsigned long long)q1 << 32);
        const unsigned long long s1b = (unsigned long long)q1 | ((unsigned long long)q2 << 32);
        #pragma unroll
        for (int k = 0; k < 16; k++) {
            int c0, c1;
            if (k < 10) { c0 = (int)((s0a >> (6 * k)) & 63ull);
                          c1 = (int)((s1a >> (6 * k)) & 63ull); }
            else        { c0 = (int)((s0b >> (6 * k - 32)) & 63ull);
                          c1 = (int)((s1b >> (6 * k - 32)) & 63ull); }
            do_step(tab + c0 * 128 + lane, x0);
            do_step(tab + c1 * 128 + lane, x1);
        }
    }

    // tail: 64 sites = 10 six-site codes + 1 four-site code
    {
        const int base = 960;
        const unsigned p0 = __ballot_sync(0xffffffffu, srow0[base      + lane] > 0.f);
        const unsigned p1 = __ballot_sync(0xffffffffu, srow0[base + 32 + lane] > 0.f);
        const unsigned q0 = __ballot_sync(0xffffffffu, srow1[base      + lane] > 0.f);
        const unsigned q1 = __ballot_sync(0xffffffffu, srow1[base + 32 + lane] > 0.f);
        const unsigned long long s0a = (unsigned long long)p0 | ((unsigned long long)p1 << 32);
        const unsigned long long s1a = (unsigned long long)q0 | ((unsigned long long)q1 << 32);
        #pragma unroll
        for (int k = 0; k < 10; k++) {
            const int c0 = (int)((s0a >> (6 * k)) & 63ull);
            const int c1 = (int)((s1a >> (6 * k)) & 63ull);
            do_step(tab + c0 * 128 + lane, x0);
            do_step(tab + c1 * 128 + lane, x1);
        }
        const int c40 = (int)((s0a >> 60) & 15ull);
        const int c41 = (int)((s1a >> 60) & 15ull);
        do_step(tab + (NC6 + c40) * 128 + lane, x0);
        do_step(tab + (NC6 + c41) * 128 + lane, x1);
    }

    // trace(M); pick this thread's diagonal elements
    float tr0 = 0.f, tr1 = 0.f;
    #pragma unroll
    for (int mt = 0; mt < 2; mt++)
        #pragma unroll
        for (int nt = 0; nt < 4; nt++)
            #pragma unroll
            for (int i = 0; i < 4; i++) {
                const int row = g + 8 * (i >> 1) + 16 * mt;
                const int col = 8 * nt + 2 * tig + (i & 1);
                if (row == col) { tr0 += x0[mt*16 + nt*4 + i];
                                  tr1 += x1[mt*16 + nt*4 + i]; }
            }
    #pragma unroll
    for (int off = 16; off; off >>= 1) {
        tr0 += __shfl_xor_sync(0xffffffffu, tr0, off);
        tr1 += __shfl_xor_sync(0xffffffffu, tr1, off);
    }

    if (lane == 0) {
        out[b0]     = logf(tr0);
        out[b0 + 1] = logf(tr1);
    }
}

// ---------------------------------------------------------------------------
extern "C" void kernel_launch(void* const* d_in, const int* in_sizes, int n_in,
                              void* d_out, int out_size) {
    const float* s = (const float*)d_in[0];   // [4096, 1024] fp32
    const float* A = (const float*)d_in[1];   // [2, 32, 32] fp32
    float* out = (float*)d_out;               // [4096] fp32

    static bool attr_set = false;
    if (!attr_set) {
        cudaFuncSetAttribute(mps_kernel,
                             cudaFuncAttributeMaxDynamicSharedMemorySize,
                             SMEM_BYTES);
        attr_set = true;
    }

    build_table_kernel<<<NC6 + NC4, 1024>>>(A);
    mps_kernel<<<GRID, 512, SMEM_BYTES>>>(s, out);
}

// round 6
// speedup vs baseline: 1.4259x; 1.0130x over previous
#include <cuda_runtime.h>
#include <cuda_bf16.h>
#include <math.h>

// Problem constants
#define NSITES 1024
#define NC6 64               // 6-site blocks: 2^6 codes
#define NC4 16               // 4-site tail block: 2^4 codes
// table entry layout (per code): 512 u32 = 128 uint4, B-fragment order
__device__ unsigned int g_table[(NC6 + NC4) * 512];   // 6-table then 4-table

// ---------------------------------------------------------------------------
// Precompute: block 0..63 -> 6-site products, block 64..79 -> 4-site products.
// Stores Y = P - I as bf16 B-fragments (deviation form for the B operand).
// ---------------------------------------------------------------------------
__global__ void build_table_kernel(const float* __restrict__ A) {
    __shared__ float M[2][32][32];
    __shared__ float P[2][32][32];
    const int tid = threadIdx.x;          // 1024 threads
    const int r = tid >> 5, c = tid & 31;

    M[0][r][c] = A[r * 32 + c];
    M[1][r][c] = A[1024 + r * 32 + c];
    __syncthreads();

    const bool is6 = blockIdx.x < NC6;
    const int code = is6 ? blockIdx.x : (blockIdx.x - NC6);
    const int nsit = is6 ? 6 : 4;

    P[0][r][c] = M[code & 1][r][c];
    __syncthreads();

    int cur = 0;
    for (int t = 1; t < nsit; t++) {
        const int bsel = (code >> t) & 1;
        float acc = 0.f;
        #pragma unroll
        for (int k = 0; k < 32; k++) acc += P[cur][r][k] * M[bsel][k][c];
        P[1 - cur][r][c] = acc;
        cur ^= 1;
        __syncthreads();
    }
    if (tid < 512) {
        const int l = tid >> 4;           // lane
        const int ridx = tid & 15;        // reg 0..15
        const int tig = l & 3, g = l >> 2;
        const int kc = ridx >> 3, nt = (ridx >> 1) & 3, h = ridx & 1;
        const int row = 16 * kc + 2 * tig + 8 * h;
        const int col = 8 * nt + g;
        const float lo = P[cur][row][col]     - (row     == col ? 1.f : 0.f);
        const float hi = P[cur][row + 1][col] - (row + 1 == col ? 1.f : 0.f);
        unsigned v;
        asm("cvt.rn.bf16x2.f32 %0, %1, %2;" : "=r"(v) : "f"(hi), "f"(lo));
        const int q = ridx >> 2, j = ridx & 3;
        g_table[blockIdx.x * 512 + q * 128 + l * 4 + j] = v;
    }
}

// ---------------------------------------------------------------------------
// Main kernel: one warp per TWO samples, hand-interleaved per step.
// M kept directly as 8 m16n8 fp32 acc fragments per sample (init = I).
// Per step:  M <- mma( bf16(M) , Y_code ) + M   ==  M @ (I + Y)   (C exact)
// NOTE: asm is NON-volatile (pure register ops) so ptxas may reschedule.
// ---------------------------------------------------------------------------
__device__ __forceinline__ void mma_bf16(float* d, const unsigned* a,
                                         unsigned b0, unsigned b1) {
    asm("mma.sync.aligned.m16n8k16.row.col.f32.bf16.bf16.f32 "
        "{%0,%1,%2,%3}, {%4,%5,%6,%7}, {%8,%9}, {%0,%1,%2,%3};"
        : "+f"(d[0]), "+f"(d[1]), "+f"(d[2]), "+f"(d[3])
        : "r"(a[0]), "r"(a[1]), "r"(a[2]), "r"(a[3]), "r"(b0), "r"(b1));
}

// Convert all 16 A fragments of one sample (reads pre-step x)
__device__ __forceinline__ void cvt_a(unsigned a[16], const float x[32]) {
    #pragma unroll
    for (int mt = 0; mt < 2; mt++)
        #pragma unroll
        for (int kc = 0; kc < 2; kc++)
            #pragma unroll
            for (int j = 0; j < 4; j++) {
                const int o = j >> 1, ih = j & 1;
                const int xi = mt * 16 + (2 * kc + o) * 4 + 2 * ih;
                asm("cvt.rn.bf16x2.f32 %0, %1, %2;"
                    : "=r"(a[mt * 8 + kc * 4 + j])
                    : "f"(x[xi + 1]), "f"(x[xi]));
            }
}

// 8 MMAs of one k-half for one sample; ta/tb are the two uint4 B tiles
__device__ __forceinline__ void mma_half(float x[32], const unsigned a[16],
                                         int abase, uint4 ta, uint4 tb) {
    #pragma unroll
    for (int mt = 0; mt < 2; mt++) {
        const unsigned* av = a + mt * 8 + abase;
        mma_bf16(x + mt*16 + 0,  av, ta.x, ta.y);
        mma_bf16(x + mt*16 + 4,  av, ta.z, ta.w);
        mma_bf16(x + mt*16 + 8,  av, tb.x, tb.y);
        mma_bf16(x + mt*16 + 12, av, tb.z, tb.w);
    }
}

// Fused two-sample step with interleaved schedule:
//   cvt a0 | lds b0 | cvt a1 | lds b1 | s0kc0 | s1kc0 | s0kc1 | s1kc1
__device__ __forceinline__ void do_step2(const uint4* __restrict__ p0,
                                         const uint4* __restrict__ p1,
                                         float x0[32], float x1[32]) {
    unsigned a0[16], a1[16];
    cvt_a(a0, x0);
    const uint4 t00 = p0[0],  t01 = p0[32], t02 = p0[64], t03 = p0[96];
    cvt_a(a1, x1);
    const uint4 t10 = p1[0],  t11 = p1[32], t12 = p1[64], t13 = p1[96];

    mma_half(x0, a0, 0, t00, t01);   // s0 kc0
    mma_half(x1, a1, 0, t10, t11);   // s1 kc0
    mma_half(x0, a0, 4, t02, t03);   // s0 kc1 (dep on s0 kc0, 8 MMAs back)
    mma_half(x1, a1, 4, t12, t13);   // s1 kc1
}

#define SMEM_BYTES ((NC6 + NC4) * 512 * 4)   // 160 KB
#define NPAIRS 2048                           // 4096 samples / 2
#define GRID 148
#define NTHREADS 448                          // 14 warps: matches pair map

__global__ void __launch_bounds__(NTHREADS, 1)
mps_kernel(const float* __restrict__ s, float* __restrict__ out) {
    extern __shared__ uint4 tab[];        // [(64+16)*128] uint4, 160 KB

    {   // cooperative copy of both tables into shared memory
        const uint4* gt = reinterpret_cast<const uint4*>(g_table);
        for (int i = threadIdx.x; i < (NC6 + NC4) * 128; i += NTHREADS)
            tab[i] = gt[i];
    }
    __syncthreads();

    const int lane = threadIdx.x & 31;
    const int warp = threadIdx.x >> 5;
    // Balanced warp->pair map over all 148 SMs
    const int pair = warp * GRID + blockIdx.x;
    if (pair >= NPAIRS) return;
    const int b0 = pair * 2;
    const int g = lane >> 2, tig = lane & 3;

    // Init M = I in C-fragment layout
    float x0[32], x1[32];
    #pragma unroll
    for (int mt = 0; mt < 2; mt++)
        #pragma unroll
        for (int nt = 0; nt < 4; nt++)
            #pragma unroll
            for (int i = 0; i < 4; i++) {
                const int row = g + 8 * (i >> 1) + 16 * mt;
                const int col = 8 * nt + 2 * tig + (i & 1);
                const float v = (row == col) ? 1.f : 0.f;
                x0[mt*16 + nt*4 + i] = v;
                x1[mt*16 + nt*4 + i] = v;
            }

    const float* srow0 = s + (size_t)b0 * NSITES;
    const float* srow1 = srow0 + NSITES;

    // 10 chunks of 96 sites = 16 six-site codes each (960 sites)
    for (int chunk = 0; chunk < 10; chunk++) {
        const int base = chunk * 96;
        const unsigned p0 = __ballot_sync(0xffffffffu, srow0[base      + lane] > 0.f);
        const unsigned p1 = __ballot_sync(0xffffffffu, srow0[base + 32 + lane] > 0.f);
        const unsigned p2 = __ballot_sync(0xffffffffu, srow0[base + 64 + lane] > 0.f);
        const unsigned q0 = __ballot_sync(0xffffffffu, srow1[base      + lane] > 0.f);
        const unsigned q1 = __ballot_sync(0xffffffffu, srow1[base + 32 + lane] > 0.f);
        const unsigned q2 = __ballot_sync(0xffffffffu, srow1[base + 64 + lane] > 0.f);
        const unsigned long long s0a = (unsigned long long)p0 | ((unsigned long long)p1 << 32);
        const unsigned long long s0b = (unsigned long long)p1 | ((unsigned long long)p2 << 32);
        const unsigned long long s1a = (unsigned long long)q0 | ((unsigned long long)q1 << 32);
        const unsigned long long s1b = (unsigned long long)q1 | ((unsigned long long)q2 << 32);
        #pragma unroll
        for (int k = 0; k < 16; k++) {
            int c0, c1;
            if (k < 10) { c0 = (int)((s0a >> (6 * k)) & 63ull);
                          c1 = (int)((s1a >> (6 * k)) & 63ull); }
            else        { c0 = (int)((s0b >> (6 * k - 32)) & 63ull);
                          c1 = (int)((s1b >> (6 * k - 32)) & 63ull); }
            do_step2(tab + c0 * 128 + lane, tab + c1 * 128 + lane, x0, x1);
        }
    }

    // tail: 64 sites = 10 six-site codes + 1 four-site code
    {
        const int base = 960;
        const unsigned p0 = __ballot_sync(0xffffffffu, srow0[base      + lane] > 0.f);
        const unsigned p1 = __ballot_sync(0xffffffffu, srow0[base + 32 + lane] > 0.f);
        const unsigned q0 = __ballot_sync(0xffffffffu, srow1[base      + lane] > 0.f);
        const unsigned q1 = __ballot_sync(0xffffffffu, srow1[base + 32 + lane] > 0.f);
        const unsigned long long s0a = (unsigned long long)p0 | ((unsigned long long)p1 << 32);
        const unsigned long long s1a = (unsigned long long)q0 | ((unsigned long long)q1 << 32);
        #pragma unroll
        for (int k = 0; k < 10; k++) {
            const int c0 = (int)((s0a >> (6 * k)) & 63ull);
            const int c1 = (int)((s1a >> (6 * k)) & 63ull);
            do_step2(tab + c0 * 128 + lane, tab + c1 * 128 + lane, x0, x1);
        }
        const int c40 = (int)((s0a >> 60) & 15ull);
        const int c41 = (int)((s1a >> 60) & 15ull);
        do_step2(tab + (NC6 + c40) * 128 + lane,
                 tab + (NC6 + c41) * 128 + lane, x0, x1);
    }

    // trace(M); pick this thread's diagonal elements
    float tr0 = 0.f, tr1 = 0.f;
    #pragma unroll
    for (int mt = 0; mt < 2; mt++)
        #pragma unroll
        for (int nt = 0; nt < 4; nt++)
            #pragma unroll
            for (int i = 0; i < 4; i++) {
                const int row = g + 8 * (i >> 1) + 16 * mt;
                const int col = 8 * nt + 2 * tig + (i & 1);
                if (row == col) { tr0 += x0[mt*16 + nt*4 + i];
                                  tr1 += x1[mt*16 + nt*4 + i]; }
            }
    #pragma unroll
    for (int off = 16; off; off >>= 1) {
        tr0 += __shfl_xor_sync(0xffffffffu, tr0, off);
        tr1 += __shfl_xor_sync(0xffffffffu, tr1, off);
    }

    if (lane == 0) {
        out[b0]     = logf(tr0);
        out[b0 + 1] = logf(tr1);
    }
}

// ---------------------------------------------------------------------------
extern "C" void kernel_launch(void* const* d_in, const int* in_sizes, int n_in,
                              void* d_out, int out_size) {
    const float* s = (const float*)d_in[0];   // [4096, 1024] fp32
    const float* A = (const float*)d_in[1];   // [2, 32, 32] fp32
    float* out = (float*)d_out;               // [4096] fp32

    static bool attr_set = false;
    if (!attr_set) {
        cudaFuncSetAttribute(mps_kernel,
                             cudaFuncAttributeMaxDynamicSharedMemorySize,
                             SMEM_BYTES);
        attr_set = true;
    }

    build_table_kernel<<<NC6 + NC4, 1024>>>(A);
    mps_kernel<<<GRID, NTHREADS, SMEM_BYTES>>>(s, out);
}

// round 8
// speedup vs baseline: 1.5714x; 1.1020x over previous
#include <cuda_runtime.h>
#include <cuda_bf16.h>
#include <math.h>

// Problem constants
#define NSITES 1024
#define NC6 64               // 6-site blocks: 2^6 codes
#define NC4 16               // 4-site tail block: 2^4 codes
// table entry layout (per code): 512 u32 = 128 uint4, B-fragment order
__device__ unsigned int g_table[(NC6 + NC4) * 512];   // 6-table then 4-table

// ---------------------------------------------------------------------------
// Precompute: block 0..63 -> 6-site products, block 64..79 -> 4-site products.
// Stores Y = P - I as bf16 B-fragments (deviation form for the B operand).
// ---------------------------------------------------------------------------
__global__ void build_table_kernel(const float* __restrict__ A) {
    __shared__ float M[2][32][32];
    __shared__ float P[2][32][32];
    const int tid = threadIdx.x;          // 1024 threads
    const int r = tid >> 5, c = tid & 31;

    M[0][r][c] = A[r * 32 + c];
    M[1][r][c] = A[1024 + r * 32 + c];
    __syncthreads();

    const bool is6 = blockIdx.x < NC6;
    const int code = is6 ? blockIdx.x : (blockIdx.x - NC6);
    const int nsit = is6 ? 6 : 4;

    P[0][r][c] = M[code & 1][r][c];
    __syncthreads();

    int cur = 0;
    for (int t = 1; t < nsit; t++) {
        const int bsel = (code >> t) & 1;
        float acc = 0.f;
        #pragma unroll
        for (int k = 0; k < 32; k++) acc += P[cur][r][k] * M[bsel][k][c];
        P[1 - cur][r][c] = acc;
        cur ^= 1;
        __syncthreads();
    }
    if (tid < 512) {
        const int l = tid >> 4;           // lane
        const int ridx = tid & 15;        // reg 0..15
        const int tig = l & 3, g = l >> 2;
        const int kc = ridx >> 3, nt = (ridx >> 1) & 3, h = ridx & 1;
        const int row = 16 * kc + 2 * tig + 8 * h;
        const int col = 8 * nt + g;
        const float lo = P[cur][row][col]     - (row     == col ? 1.f : 0.f);
        const float hi = P[cur][row + 1][col] - (row + 1 == col ? 1.f : 0.f);
        unsigned v;
        asm("cvt.rn.bf16x2.f32 %0, %1, %2;" : "=r"(v) : "f"(hi), "f"(lo));
        const int q = ridx >> 2, j = ridx & 3;
        g_table[blockIdx.x * 512 + q * 128 + l * 4 + j] = v;
    }
}

// ---------------------------------------------------------------------------
// Main kernel: ONE sample per warp, 28 warps/CTA, 1 CTA/SM.
// M kept directly as 8 m16n8 fp32 acc fragments (init = I).
// Per step:  M <- mma( bf16(M) , Y_code ) + M   ==  M @ (I + Y)   (C exact)
// ---------------------------------------------------------------------------
__device__ __forceinline__ void mma_bf16(float* d, const unsigned* a,
                                         unsigned b0, unsigned b1) {
    asm("mma.sync.aligned.m16n8k16.row.col.f32.bf16.bf16.f32 "
        "{%0,%1,%2,%3}, {%4,%5,%6,%7}, {%8,%9}, {%0,%1,%2,%3};"
        : "+f"(d[0]), "+f"(d[1]), "+f"(d[2]), "+f"(d[3])
        : "r"(a[0]), "r"(a[1]), "r"(a[2]), "r"(a[3]), "r"(b0), "r"(b1));
}

// Convert all 16 A fragments (reads pre-step x; must complete before MMAs)
__device__ __forceinline__ void cvt_a(unsigned a[16], const float x[32]) {
    #pragma unroll
    for (int mt = 0; mt < 2; mt++)
        #pragma unroll
        for (int kc = 0; kc < 2; kc++)
            #pragma unroll
            for (int j = 0; j < 4; j++) {
                const int o = j >> 1, ih = j & 1;
                const int xi = mt * 16 + (2 * kc + o) * 4 + 2 * ih;
                asm("cvt.rn.bf16x2.f32 %0, %1, %2;"
                    : "=r"(a[mt * 8 + kc * 4 + j])
                    : "f"(x[xi + 1]), "f"(x[xi]));
            }
}

// 8 MMAs of one k-half; ta/tb are the two uint4 B tiles for this half
__device__ __forceinline__ void mma_half(float x[32], const unsigned a[16],
                                         int abase, uint4 ta, uint4 tb) {
    #pragma unroll
    for (int mt = 0; mt < 2; mt++) {
        const unsigned* av = a + mt * 8 + abase;
        mma_bf16(x + mt*16 + 0,  av, ta.x, ta.y);
        mma_bf16(x + mt*16 + 4,  av, ta.z, ta.w);
        mma_bf16(x + mt*16 + 8,  av, tb.x, tb.y);
        mma_bf16(x + mt*16 + 12, av, tb.z, tb.w);
    }
}

// One 6/4-site step, b tiles staged per k-half to shorten register liveness
__device__ __forceinline__ void do_step(const uint4* __restrict__ p,
                                        float x[32]) {
    unsigned a[16];
    cvt_a(a, x);
    {
        const uint4 t0 = p[0], t1 = p[32];
        mma_half(x, a, 0, t0, t1);        // kc0
    }
    {
        const uint4 t2 = p[64], t3 = p[96];
        mma_half(x, a, 4, t2, t3);        // kc1
    }
}

#define SMEM_BYTES ((NC6 + NC4) * 512 * 4)   // 160 KB
#define GRID 148
#define NTHREADS 896                          // 28 warps, ~73 reg ceiling

__global__ void __launch_bounds__(NTHREADS, 1)
mps_kernel(const float* __restrict__ s, float* __restrict__ out) {
    extern __shared__ uint4 tab[];        // [(64+16)*128] uint4, 160 KB

    {   // cooperative copy of both tables into shared memory
        const uint4* gt = reinterpret_cast<const uint4*>(g_table);
        for (int i = threadIdx.x; i < (NC6 + NC4) * 128; i += NTHREADS)
            tab[i] = gt[i];
    }
    __syncthreads();

    const int lane = threadIdx.x & 31;
    const int warp = threadIdx.x >> 5;
    // Balanced warp->sample map over all 148 SMs (28*148 = 4144 >= 4096)
    const int b = warp * GRID + blockIdx.x;
    if (b >= 4096) return;
    const int g = lane >> 2, tig = lane & 3;

    // Init M = I in C-fragment layout
    float x[32];
    #pragma unroll
    for (int mt = 0; mt < 2; mt++)
        #pragma unroll
        for (int nt = 0; nt < 4; nt++)
            #pragma unroll
            for (int i = 0; i < 4; i++) {
                const int row = g + 8 * (i >> 1) + 16 * mt;
                const int col = 8 * nt + 2 * tig + (i & 1);
                x[mt*16 + nt*4 + i] = (row == col) ? 1.f : 0.f;
            }

    const float* srow = s + (size_t)b * NSITES;

    // 10 chunks of 96 sites = 16 six-site codes each (960 sites)
    for (int chunk = 0; chunk < 10; chunk++) {
        const int base = chunk * 96;
        const unsigned m0 = __ballot_sync(0xffffffffu, srow[base      + lane] > 0.f);
        const unsigned m1 = __ballot_sync(0xffffffffu, srow[base + 32 + lane] > 0.f);
        const unsigned m2 = __ballot_sync(0xffffffffu, srow[base + 64 + lane] > 0.f);
        const unsigned long long u01 = (unsigned long long)m0 |
                                       ((unsigned long long)m1 << 32);
        const unsigned long long u12 = (unsigned long long)m1 |
                                       ((unsigned long long)m2 << 32);
        #pragma unroll
        for (int k = 0; k < 16; k++) {
            int code;
            if (k < 10) code = (int)((u01 >> (6 * k)) & 63ull);
            else        code = (int)((u12 >> (6 * k - 32)) & 63ull);
            do_step(tab + code * 128 + lane, x);
        }
    }

    // tail: 64 sites = 10 six-site codes + 1 four-site code
    {
        const int base = 960;
        const unsigned m0 = __ballot_sync(0xffffffffu, srow[base      + lane] > 0.f);
        const unsigned m1 = __ballot_sync(0xffffffffu, srow[base + 32 + lane] > 0.f);
        const unsigned long long u01 = (unsigned long long)m0 |
                                       ((unsigned long long)m1 << 32);
        #pragma unroll
        for (int k = 0; k < 10; k++) {
            const int code = (int)((u01 >> (6 * k)) & 63ull);
            do_step(tab + code * 128 + lane, x);
        }
        const int c4 = (int)((u01 >> 60) & 15ull);
        do_step(tab + (NC6 + c4) * 128 + lane, x);
    }

    // trace(M); pick this thread's diagonal elements
    float tr = 0.f;
    #pragma unroll
    for (int mt = 0; mt < 2; mt++)
        #pragma unroll
        for (int nt = 0; nt < 4; nt++)
            #pragma unroll
            for (int i = 0; i < 4; i++) {
                const int row = g + 8 * (i >> 1) + 16 * mt;
                const int col = 8 * nt + 2 * tig + (i & 1);
                if (row == col) tr += x[mt*16 + nt*4 + i];
            }
    #pragma unroll
    for (int off = 16; off; off >>= 1)
        tr += __shfl_xor_sync(0xffffffffu, tr, off);

    if (lane == 0) out[b] = logf(tr);
}

// ---------------------------------------------------------------------------
extern "C" void kernel_launch(void* const* d_in, const int* in_sizes, int n_in,
                              void* d_out, int out_size) {
    const float* s = (const float*)d_in[0];   // [4096, 1024] fp32
    const float* A = (const float*)d_in[1];   // [2, 32, 32] fp32
    float* out = (float*)d_out;               // [4096] fp32

    static bool attr_set = false;
    if (!attr_set) {
        cudaFuncSetAttribute(mps_kernel,
                             cudaFuncAttributeMaxDynamicSharedMemorySize,
                             SMEM_BYTES);
        attr_set = true;
    }

    build_table_kernel<<<NC6 + NC4, 1024>>>(A);
    mps_kernel<<<GRID, NTHREADS, SMEM_BYTES>>>(s, out);
}

// round 9
// speedup vs baseline: 1.5842x; 1.0082x over previous
#include <cuda_runtime.h>
#include <cuda_bf16.h>
#include <math.h>

// Problem constants
#define NSITES 1024
#define NC6 64               // 6-site blocks: 2^6 codes
#define NC4 16               // 4-site tail block: 2^4 codes
// table entry layout (per code): 512 u32 = 128 uint4, B-fragment order
__device__ unsigned int g_table[(NC6 + NC4) * 512];   // 6-table then 4-table

// ---------------------------------------------------------------------------
// Precompute: block 0..63 -> 6-site products, block 64..79 -> 4-site products.
// Stores Y = P - I as bf16 B-fragments (deviation form for the B operand).
// ---------------------------------------------------------------------------
__global__ void build_table_kernel(const float* __restrict__ A) {
    __shared__ float M[2][32][32];
    __shared__ float P[2][32][32];
    const int tid = threadIdx.x;          // 1024 threads
    const int r = tid >> 5, c = tid & 31;

    M[0][r][c] = A[r * 32 + c];
    M[1][r][c] = A[1024 + r * 32 + c];
    __syncthreads();

    const bool is6 = blockIdx.x < NC6;
    const int code = is6 ? blockIdx.x : (blockIdx.x - NC6);
    const int nsit = is6 ? 6 : 4;

    P[0][r][c] = M[code & 1][r][c];
    __syncthreads();

    int cur = 0;
    for (int t = 1; t < nsit; t++) {
        const int bsel = (code >> t) & 1;
        float acc = 0.f;
        #pragma unroll
        for (int k = 0; k < 32; k++) acc += P[cur][r][k] * M[bsel][k][c];
        P[1 - cur][r][c] = acc;
        cur ^= 1;
        __syncthreads();
    }
    if (tid < 512) {
        const int l = tid >> 4;           // lane
        const int ridx = tid & 15;        // reg 0..15
        const int tig = l & 3, g = l >> 2;
        const int kc = ridx >> 3, nt = (ridx >> 1) & 3, h = ridx & 1;
        const int row = 16 * kc + 2 * tig + 8 * h;
        const int col = 8 * nt + g;
        const float lo = P[cur][row][col]     - (row     == col ? 1.f : 0.f);
        const float hi = P[cur][row + 1][col] - (row + 1 == col ? 1.f : 0.f);
        unsigned v;
        asm("cvt.rn.bf16x2.f32 %0, %1, %2;" : "=r"(v) : "f"(hi), "f"(lo));
        const int q = ridx >> 2, j = ridx & 3;
        g_table[blockIdx.x * 512 + q * 128 + l * 4 + j] = v;
    }
}

// ---------------------------------------------------------------------------
// Main kernel: ONE sample per warp, 28 warps/CTA, 1 CTA/SM.
// Prologue: all 32 sign-mask words per warp computed once (LDG+ballot) and
// stashed in smem -> steady-state loop has NO global loads / ballots.
// Per step:  M <- mma( bf16(M) , Y_code ) + M   ==  M @ (I + Y)   (C exact)
// ---------------------------------------------------------------------------
__device__ __forceinline__ void mma_bf16(float* d, const unsigned* a,
                                         unsigned b0, unsigned b1) {
    asm("mma.sync.aligned.m16n8k16.row.col.f32.bf16.bf16.f32 "
        "{%0,%1,%2,%3}, {%4,%5,%6,%7}, {%8,%9}, {%0,%1,%2,%3};"
        : "+f"(d[0]), "+f"(d[1]), "+f"(d[2]), "+f"(d[3])
        : "r"(a[0]), "r"(a[1]), "r"(a[2]), "r"(a[3]), "r"(b0), "r"(b1));
}

// Convert all 16 A fragments (reads pre-step x; must complete before MMAs)
__device__ __forceinline__ void cvt_a(unsigned a[16], const float x[32]) {
    #pragma unroll
    for (int mt = 0; mt < 2; mt++)
        #pragma unroll
        for (int kc = 0; kc < 2; kc++)
            #pragma unroll
            for (int j = 0; j < 4; j++) {
                const int o = j >> 1, ih = j & 1;
                const int xi = mt * 16 + (2 * kc + o) * 4 + 2 * ih;
                asm("cvt.rn.bf16x2.f32 %0, %1, %2;"
                    : "=r"(a[mt * 8 + kc * 4 + j])
                    : "f"(x[xi + 1]), "f"(x[xi]));
            }
}

// 8 MMAs of one k-half; ta/tb are the two uint4 B tiles for this half
__device__ __forceinline__ void mma_half(float x[32], const unsigned a[16],
                                         int abase, uint4 ta, uint4 tb) {
    #pragma unroll
    for (int mt = 0; mt < 2; mt++) {
        const unsigned* av = a + mt * 8 + abase;
        mma_bf16(x + mt*16 + 0,  av, ta.x, ta.y);
        mma_bf16(x + mt*16 + 4,  av, ta.z, ta.w);
        mma_bf16(x + mt*16 + 8,  av, tb.x, tb.y);
        mma_bf16(x + mt*16 + 12, av, tb.z, tb.w);
    }
}

// One 6/4-site step, b tiles staged per k-half to shorten register liveness
__device__ __forceinline__ void do_step(const uint4* __restrict__ p,
                                        float x[32]) {
    unsigned a[16];
    cvt_a(a, x);
    {
        const uint4 t0 = p[0], t1 = p[32];
        mma_half(x, a, 0, t0, t1);        // kc0
    }
    {
        const uint4 t2 = p[64], t3 = p[96];
        mma_half(x, a, 4, t2, t3);        // kc1
    }
}

#define TAB_BYTES ((NC6 + NC4) * 512 * 4)     // 160 KB
#define NWARPS 28
#define MSK_BYTES (NWARPS * 32 * 4)           // 3.5 KB
#define SMEM_BYTES (TAB_BYTES + MSK_BYTES)
#define GRID 148
#define NTHREADS (NWARPS * 32)                // 896 threads

__global__ void __launch_bounds__(NTHREADS, 1)
mps_kernel(const float* __restrict__ s, float* __restrict__ out) {
    extern __shared__ unsigned char smem_raw[];
    uint4* tab = reinterpret_cast<uint4*>(smem_raw);
    unsigned* msk = reinterpret_cast<unsigned*>(smem_raw + TAB_BYTES);

    {   // cooperative copy of both tables into shared memory
        const uint4* gt = reinterpret_cast<const uint4*>(g_table);
        for (int i = threadIdx.x; i < (NC6 + NC4) * 128; i += NTHREADS)
            tab[i] = gt[i];
    }

    const int lane = threadIdx.x & 31;
    const int warp = threadIdx.x >> 5;
    // Balanced warp->sample map over all 148 SMs (28*148 = 4144 >= 4096)
    const int b = warp * GRID + blockIdx.x;
    const int g = lane >> 2, tig = lane & 3;

    // Prologue: compute all 32 sign-mask words for this warp, stash in smem.
    // (masks are per-warp private; no cross-warp sync needed for them)
    if (b < 4096) {
        const float* srow = s + (size_t)b * NSITES;
        unsigned* mw = msk + warp * 32;
        #pragma unroll 8
        for (int j = 0; j < 32; j++)
            mw[j] = __ballot_sync(0xffffffffu, srow[j * 32 + lane] > 0.f);
    }
    __syncthreads();            // table ready (and masks written)
    if (b >= 4096) return;

    // Init M = I in C-fragment layout
    float x[32];
    #pragma unroll
    for (int mt = 0; mt < 2; mt++)
        #pragma unroll
        for (int nt = 0; nt < 4; nt++)
            #pragma unroll
            for (int i = 0; i < 4; i++) {
                const int row = g + 8 * (i >> 1) + 16 * mt;
                const int col = 8 * nt + 2 * tig + (i & 1);
                x[mt*16 + nt*4 + i] = (row == col) ? 1.f : 0.f;
            }

    const unsigned* mw = msk + warp * 32;

    // 10 chunks of 96 sites = 16 six-site codes each (960 sites)
    for (int chunk = 0; chunk < 10; chunk++) {
        const unsigned m0 = mw[3 * chunk + 0];
        const unsigned m1 = mw[3 * chunk + 1];
        const unsigned m2 = mw[3 * chunk + 2];
        const unsigned long long u01 = (unsigned long long)m0 |
                                       ((unsigned long long)m1 << 32);
        const unsigned long long u12 = (unsigned long long)m1 |
                                       ((unsigned long long)m2 << 32);
        #pragma unroll
        for (int k = 0; k < 16; k++) {
            int code;
            if (k < 10) code = (int)((u01 >> (6 * k)) & 63ull);
            else        code = (int)((u12 >> (6 * k - 32)) & 63ull);
            do_step(tab + code * 128 + lane, x);
        }
    }

    // tail: 64 sites = 10 six-site codes + 1 four-site code
    {
        const unsigned m0 = mw[30];
        const unsigned m1 = mw[31];
        const unsigned long long u01 = (unsigned long long)m0 |
                                       ((unsigned long long)m1 << 32);
        #pragma unroll
        for (int k = 0; k < 10; k++) {
            const int code = (int)((u01 >> (6 * k)) & 63ull);
            do_step(tab + code * 128 + lane, x);
        }
        const int c4 = (int)((u01 >> 60) & 15ull);
        do_step(tab + (NC6 + c4) * 128 + lane, x);
    }

    // trace(M); pick this thread's diagonal elements
    float tr = 0.f;
    #pragma unroll
    for (int mt = 0; mt < 2; mt++)
        #pragma unroll
        for (int nt = 0; nt < 4; nt++)
            #pragma unroll
            for (int i = 0; i < 4; i++) {
                const int row = g + 8 * (i >> 1) + 16 * mt;
                const int col = 8 * nt + 2 * tig + (i & 1);
                if (row == col) tr += x[mt*16 + nt*4 + i];
            }
    #pragma unroll
    for (int off = 16; off; off >>= 1)
        tr += __shfl_xor_sync(0xffffffffu, tr, off);

    if (lane == 0) out[b] = logf(tr);
}

// ---------------------------------------------------------------------------
extern "C" void kernel_launch(void* const* d_in, const int* in_sizes, int n_in,
                              void* d_out, int out_size) {
    const float* s = (const float*)d_in[0];   // [4096, 1024] fp32
    const float* A = (const float*)d_in[1];   // [2, 32, 32] fp32
    float* out = (float*)d_out;               // [4096] fp32

    static bool attr_set = false;
    if (!attr_set) {
        cudaFuncSetAttribute(mps_kernel,
                             cudaFuncAttributeMaxDynamicSharedMemorySize,
                             SMEM_BYTES);
        attr_set = true;
    }

    build_table_kernel<<<NC6 + NC4, 1024>>>(A);
    mps_kernel<<<GRID, NTHREADS, SMEM_BYTES>>>(s, out);
}